// round 10
// baseline (speedup 1.0000x reference)
#include <cuda_runtime.h>
#include <cuda_bf16.h>
#include <cstdint>

typedef unsigned long long u64;

// Problem constants
#define B 4
#define C 4
#define H 256
#define W 256
#define HW (H*W)          // 65536
#define FS 11
#define PAD 5

// Tile config
#define BW 32             // tile width (output pixels)
#define BH 8              // tile height
#define R  2              // pixels per thread along w
#define NTHREADS 128      // (BW/R) * BH = 16 * 8
#define HALO_W (BW + FS - 1)   // 42
#define HALO_H (BH + FS - 1)   // 18
#define NHALO (HALO_H * HALO_W)  // 756
#define NHIT ((NHALO + NTHREADS - 1) / NTHREADS)   // 6
#define SST 43            // shared row stride in 16B units (bank-skewed)

__device__ __forceinline__ float ex2(float s) {
    float r;
    asm("ex2.approx.f32 %0, %1;" : "=f"(r) : "f"(s));
    return r;
}
__device__ __forceinline__ u64 fma2(u64 a, u64 b, u64 c) {
    u64 d;
    asm("fma.rn.f32x2 %0, %1, %2, %3;" : "=l"(d) : "l"(a), "l"(b), "l"(c));
    return d;
}
__device__ __forceinline__ u64 mul2(u64 a, u64 b) {
    u64 d;
    asm("mul.rn.f32x2 %0, %1, %2;" : "=l"(d) : "l"(a), "l"(b));
    return d;
}
__device__ __forceinline__ u64 packf2(float a, float b) {
    u64 d;
    asm("mov.b64 %0, {%1, %2};" : "=l"(d) : "f"(a), "f"(b));
    return d;
}
__device__ __forceinline__ float2 unpack2(u64 v) {
    float2 f;
    asm("mov.b64 {%0, %1}, %2;" : "=f"(f.x), "=f"(f.y) : "l"(v));
    return f;
}

// ---------------------------------------------------------------------------
// Single fused kernel, algebraically folded:
//   score_k = psi . x_k   with  psi = (Wp^T Wt) x_p  (pre-scaled by log2 e)
//   out     = M (sum_k att_k x_k) + x,  M = Ww Wg
// Score: packed f32x2 (operands naturally pair-aligned -> no MOVs).
// Accumulate: SCALAR FFMA with scalar e (no dup2 broadcast, no repacks).
// ---------------------------------------------------------------------------
__global__ __launch_bounds__(NTHREADS) void fused_kernel(
    const float* __restrict__ x,
    const float* __restrict__ Wt,
    const float* __restrict__ Wp,
    const float* __restrict__ Wg,
    const float* __restrict__ Ww,
    float* __restrict__ out)
{
    __shared__ ulonglong2 xsh[HALO_H * SST];   // x halo: (c01, c23) f32 pairs
    __shared__ float wN[16];                   // N = Wp^T Wt, scaled by log2 e
    __shared__ float wM[16];                   // M = Ww Wg

    int tid = threadIdx.x;

    int b  = blockIdx.z;
    int h0 = blockIdx.y * BH;
    int w0 = blockIdx.x * BW;
    const float* xb = x + b * (C * HW);

    // --- Small matrix products N, M (threads 0..31, one entry each) ---
    if (tid < 32) {
        int e = tid & 15;
        int i = e >> 2;       // row
        int j = e & 3;        // col
        if (tid < 16) {
            float s = Wp[i] * Wt[j];
            s = fmaf(Wp[4 + i],  Wt[4 + j],  s);
            s = fmaf(Wp[8 + i],  Wt[8 + j],  s);
            s = fmaf(Wp[12 + i], Wt[12 + j], s);
            wN[e] = s * 1.4426950408889634f;
        } else {
            float s = Ww[i*4 + 0] * Wg[j];
            s = fmaf(Ww[i*4 + 1], Wg[4 + j],  s);
            s = fmaf(Ww[i*4 + 2], Wg[8 + j],  s);
            s = fmaf(Ww[i*4 + 3], Wg[12 + j], s);
            wM[e] = s;
        }
    }

    // --- Halo: batch ALL global loads first (MLP), then shared stores ---
    float v0[NHIT], v1[NHIT], v2[NHIT], v3[NHIT];
    #pragma unroll
    for (int it = 0; it < NHIT; it++) {
        int idx = it * NTHREADS + tid;
        v0[it] = 0.f; v1[it] = 0.f; v2[it] = 0.f; v3[it] = 0.f;
        if (idx < NHALO) {
            int i  = idx / HALO_W;
            int j  = idx - i * HALO_W;
            int gh = h0 - PAD + i;
            int gw = w0 - PAD + j;
            if ((unsigned)gh < (unsigned)H && (unsigned)gw < (unsigned)W) {
                const float* xp = xb + gh * W + gw;
                v0[it] = xp[0];
                v1[it] = xp[HW];
                v2[it] = xp[2*HW];
                v3[it] = xp[3*HW];
            }
        }
    }
    #pragma unroll
    for (int it = 0; it < NHIT; it++) {
        int idx = it * NTHREADS + tid;
        if (idx < NHALO) {
            int i  = idx / HALO_W;
            int j  = idx - i * HALO_W;
            xsh[i * SST + j] = make_ulonglong2(packf2(v0[it], v1[it]),
                                               packf2(v2[it], v3[it]));
        }
    }

    // --- Own-pixel x loads (for psi and residual) ---
    // Lane mapping: ty = lane&1 (+2 per warp), tx = (lane>>1)&15.
    // Conflict-free 8-lane LDS.128 phases given SST=43.
    int tx = (tid >> 1) & 15;
    int ty = ((tid >> 5) << 1) | (tid & 1);
    int oh = h0 + ty;
    int ow = w0 + tx * R;
    int pixbase = oh * W + ow;

    float xs[4][R];
    #pragma unroll
    for (int c = 0; c < 4; c++) {
        float2 v = *(const float2*)(xb + c * HW + pixbase);
        xs[c][0] = v.x; xs[c][1] = v.y;
    }
    __syncthreads();

    // --- psi = N x_p (per own pixel), packed as f32x2 pairs ---
    u64 psiA[R], psiB[R];
    float acc0[R], acc1[R], acc2[R], acc3[R], sum[R];
    #pragma unroll
    for (int r = 0; r < R; r++) {
        float p0 = fmaf(wN[0],  xs[0][r], fmaf(wN[1],  xs[1][r], fmaf(wN[2],  xs[2][r], wN[3]  * xs[3][r])));
        float p1 = fmaf(wN[4],  xs[0][r], fmaf(wN[5],  xs[1][r], fmaf(wN[6],  xs[2][r], wN[7]  * xs[3][r])));
        float p2 = fmaf(wN[8],  xs[0][r], fmaf(wN[9],  xs[1][r], fmaf(wN[10], xs[2][r], wN[11] * xs[3][r])));
        float p3 = fmaf(wN[12], xs[0][r], fmaf(wN[13], xs[1][r], fmaf(wN[14], xs[2][r], wN[15] * xs[3][r])));
        psiA[r] = packf2(p0, p1);
        psiB[r] = packf2(p2, p3);
        acc0[r] = 0.f; acc1[r] = 0.f; acc2[r] = 0.f; acc3[r] = 0.f;
        sum[r] = 0.f;
    }

    int base = ty * SST + tx * R;

    // --- Main loop: packed score, scalar accumulate (no MOV tax) ---
    #pragma unroll 1
    for (int ki = 0; ki < FS; ki++) {
        const ulonglong2* row = &xsh[base + ki * SST];
        ulonglong2 xw[4];
        xw[0] = row[0]; xw[1] = row[1]; xw[2] = row[2];
        #pragma unroll
        for (int kj = 0; kj < FS; kj++) {
            if (kj < 9) xw[(kj + 3) & 3] = row[kj + 3];   // compile-time guard
            #pragma unroll
            for (int r = 0; r < R; r++) {
                ulonglong2 X = xw[(kj + r) & 3];
                u64 t = mul2(psiA[r], X.x);
                t = fma2(psiB[r], X.y, t);
                float2 f = unpack2(t);
                float e = ex2(f.x + f.y);       // psi pre-scaled by log2 e
                sum[r] += e;
                float2 xa = unpack2(X.x);       // pure register renaming
                float2 xc = unpack2(X.y);
                acc0[r] = fmaf(e, xa.x, acc0[r]);
                acc1[r] = fmaf(e, xa.y, acc1[r]);
                acc2[r] = fmaf(e, xc.x, acc2[r]);
                acc3[r] = fmaf(e, xc.y, acc3[r]);
            }
        }
    }

    // --- Epilogue: normalize, apply M, residual; float2 stores ---
    float a0[R], a1[R], a2[R], a3[R];
    #pragma unroll
    for (int r = 0; r < R; r++) {
        float inv = __frcp_rn(sum[r]);
        a0[r] = acc0[r] * inv;
        a1[r] = acc1[r] * inv;
        a2[r] = acc2[r] * inv;
        a3[r] = acc3[r] * inv;
    }
    float* ob = out + b * (C * HW);
    #pragma unroll
    for (int c = 0; c < C; c++) {
        float2 res;
        res.x = fmaf(wM[c*4+0], a0[0], fmaf(wM[c*4+1], a1[0], fmaf(wM[c*4+2], a2[0], wM[c*4+3] * a3[0]))) + xs[c][0];
        res.y = fmaf(wM[c*4+0], a0[1], fmaf(wM[c*4+1], a1[1], fmaf(wM[c*4+2], a2[1], wM[c*4+3] * a3[1]))) + xs[c][1];
        *(float2*)(ob + c * HW + pixbase) = res;
    }
}

// ---------------------------------------------------------------------------
extern "C" void kernel_launch(void* const* d_in, const int* in_sizes, int n_in,
                              void* d_out, int out_size)
{
    const float* x  = (const float*)d_in[0];
    const float* Wt = (const float*)d_in[1];
    const float* Wp = (const float*)d_in[2];
    const float* Wg = (const float*)d_in[3];
    const float* Ww = (const float*)d_in[4];
    float* out = (float*)d_out;

    dim3 grid(W / BW, H / BH, B);
    fused_kernel<<<grid, NTHREADS>>>(x, Wt, Wp, Wg, Ww, out);
}